// round 4
// baseline (speedup 1.0000x reference)
#include <cuda_runtime.h>
#include <cstdint>

#define KDIM  8192
#define N4    6144
#define N8    2048
#define NTOT  8192
#define MROWS 16
#define KSEGS 16
#define KSEG  512          // KDIM / KSEGS
#define NBLK  16           // 12 int4 + 4 int8 column blocks
#define TPB   256
#define CPB   512          // columns per block (2 per thread)

typedef unsigned long long ull;

// Scratch (device globals; no runtime allocation)
__device__ __align__(16) ull   g_x2p[KDIM / 2][MROWS];           // 512 KB, k-pair packed x2, [kp][m]
__device__ __align__(16) float g_part[KSEGS][MROWS][NTOT];       // 8 MB partial slabs

// ---- Blackwell packed fp32 ops (sm_100+; ptxas never auto-emits these) ----
__device__ __forceinline__ ull ffma2(ull a, ull b, ull c) {
    ull d;
    asm("fma.rn.f32x2 %0, %1, %2, %3;" : "=l"(d) : "l"(a), "l"(b), "l"(c));
    return d;
}
__device__ __forceinline__ ull fadd2(ull a, ull b) {
    ull d;
    asm("add.rn.f32x2 %0, %1, %2;" : "=l"(d) : "l"(a), "l"(b));
    return d;
}
__device__ __forceinline__ ull fmul2(ull a, ull b) {
    ull d;
    asm("mul.rn.f32x2 %0, %1, %2;" : "=l"(d) : "l"(a), "l"(b));
    return d;
}
__device__ __forceinline__ ull pack2(float lo, float hi) {
    ull r;
    asm("mov.b64 %0, {%1, %2};" : "=l"(r) : "f"(lo), "f"(hi));
    return r;
}
__device__ __forceinline__ float2 unpack2(ull v) {
    float2 f;
    asm("mov.b64 {%0, %1}, %2;" : "=f"(f.x), "=f"(f.y) : "l"(v));
    return f;
}
// int (0 <= w < 2^22) -> float(2^23 + w), exact, one LOP3
__device__ __forceinline__ float biasf(int w) {
    return __uint_as_float(0x4B000000u | (unsigned)w);
}

// ---------------- Kernel 1: transpose + scale: g_x2p[kp][m] = pack(x[m][2kp]/awq, x[m][2kp+1]/awq) ----------------
__global__ void prep_kernel(const float* __restrict__ x, const float* __restrict__ awq) {
    const int idx = blockIdx.x * blockDim.x + threadIdx.x;   // 16384 threads
    const int mq = idx & 3;          // m-quad 0..3
    const int kp = idx >> 2;         // 0..4095
    const float2 a = *reinterpret_cast<const float2*>(awq + 2 * kp);
    ull p[4];
    #pragma unroll
    for (int i = 0; i < 4; i++) {
        const int m = mq * 4 + i;
        const float2 xv = *reinterpret_cast<const float2*>(x + (size_t)m * KDIM + 2 * kp);
        p[i] = pack2(xv.x / a.x, xv.y / a.y);
    }
    ulonglong2* dst = reinterpret_cast<ulonglong2*>(&g_x2p[kp][mq * 4]);
    dst[0] = make_ulonglong2(p[0], p[1]);
    dst[1] = make_ulonglong2(p[2], p[3]);
}

// ---------------- Kernel 2: mixed int4/int8 GEMV ----------------
// grid = (NBLK, KSEGS). Blocks 0..11: int4 cols. Blocks 12..15: uint8 cols.
// 2 cols/thread; 16 m accumulators per column, k-pair packed f32x2.
__global__ void __launch_bounds__(TPB, 2) gemv_kernel(
    const int4* __restrict__ w4,   // w_int4 as int4 vectors
    const float* __restrict__ s4,  // s_int4 [N4][64]
    const int4* __restrict__ w8)   // w_uint8 as int4 vectors
{
    __shared__ ull xs[KSEG / 2][MROWS];   // 256 x 16 x 8B = 32 KB

    const int nb  = blockIdx.x;
    const int ks  = blockIdx.y;
    const int k0  = ks * KSEG;
    const int tid = threadIdx.x;

    // Stage x k-pair tile: contiguous 32 KB copy
    {
        const ulonglong2* src = reinterpret_cast<const ulonglong2*>(&g_x2p[k0 / 2][0]);
        ulonglong2* dst = reinterpret_cast<ulonglong2*>(&xs[0][0]);
        #pragma unroll
        for (int i = tid; i < (KSEG / 2) * MROWS / 2; i += TPB)
            dst[i] = src[i];
    }
    __syncthreads();

    ull acc0[MROWS], acc1[MROWS];
    #pragma unroll
    for (int m = 0; m < MROWS; m++) { acc0[m] = 0ull; acc1[m] = 0ull; }

    if (nb < 12) {
        // ---------------- int4 path ----------------
        const int n0 = nb * CPB + tid;
        const int n1 = n0 + TPB;
        const int4* r0 = w4 + ((size_t)n0 * KDIM + k0) / 4;
        const int4* r1 = w4 + ((size_t)n1 * KDIM + k0) / 4;
        const ull C4 = pack2(-8388616.0f, -8388616.0f);   // -(2^23 + 8)

        int4 wa = __ldcs(r0);
        int4 wb = __ldcs(r1);

        #pragma unroll
        for (int g = 0; g < KSEG / 128; g++) {            // 4 groups of 128 k
            const float sa = s4[n0 * (KDIM / 128) + (k0 >> 7) + g];
            const float sb = s4[n1 * (KDIM / 128) + (k0 >> 7) + g];
            const ull sap = pack2(sa, sa);
            const ull sbp = pack2(sb, sb);

            #pragma unroll 4
            for (int it = 0; it < 32; it++) {             // 4 k per iteration
                const int idx = g * 32 + it;
                // prefetch next iteration's weights
                int4 wa_n, wb_n;
                if (idx < (KSEG / 4) - 1) {
                    wa_n = __ldcs(r0 + idx + 1);
                    wb_n = __ldcs(r1 + idx + 1);
                } else {
                    wa_n = wa; wb_n = wb;
                }

                // dequant, exact: ((2^23+w) - (2^23+8)) * s, k-pair packed
                const ull a01 = fmul2(fadd2(pack2(biasf(wa.x), biasf(wa.y)), C4), sap);
                const ull a23 = fmul2(fadd2(pack2(biasf(wa.z), biasf(wa.w)), C4), sap);
                const ull b01 = fmul2(fadd2(pack2(biasf(wb.x), biasf(wb.y)), C4), sbp);
                const ull b23 = fmul2(fadd2(pack2(biasf(wb.z), biasf(wb.w)), C4), sbp);

                const int kp = idx * 2;
                #pragma unroll
                for (int mq = 0; mq < MROWS / 2; mq++) {
                    const ulonglong2 xA = *reinterpret_cast<const ulonglong2*>(&xs[kp][2 * mq]);
                    const ulonglong2 xB = *reinterpret_cast<const ulonglong2*>(&xs[kp + 1][2 * mq]);
                    acc0[2 * mq]     = ffma2(xA.x, a01, acc0[2 * mq]);
                    acc0[2 * mq + 1] = ffma2(xA.y, a01, acc0[2 * mq + 1]);
                    acc0[2 * mq]     = ffma2(xB.x, a23, acc0[2 * mq]);
                    acc0[2 * mq + 1] = ffma2(xB.y, a23, acc0[2 * mq + 1]);
                    acc1[2 * mq]     = ffma2(xA.x, b01, acc1[2 * mq]);
                    acc1[2 * mq + 1] = ffma2(xA.y, b01, acc1[2 * mq + 1]);
                    acc1[2 * mq]     = ffma2(xB.x, b23, acc1[2 * mq]);
                    acc1[2 * mq + 1] = ffma2(xB.y, b23, acc1[2 * mq + 1]);
                }
                wa = wa_n; wb = wb_n;
            }
        }

        float* dst = &g_part[ks][0][0];
        #pragma unroll
        for (int m = 0; m < MROWS; m++) {
            float2 t0 = unpack2(acc0[m]);
            float2 t1 = unpack2(acc1[m]);
            dst[m * NTOT + n0] = t0.x + t0.y;
            dst[m * NTOT + n1] = t1.x + t1.y;
        }
    } else {
        // ---------------- uint8 path: sum x2*(w-128); s8 deferred ----------------
        const int nl0 = (nb - 12) * CPB + tid;
        const int nl1 = nl0 + TPB;
        const int4* r0 = w8 + ((size_t)nl0 * KDIM + k0) / 4;
        const int4* r1 = w8 + ((size_t)nl1 * KDIM + k0) / 4;
        const ull C8 = pack2(-8388736.0f, -8388736.0f);   // -(2^23 + 128)

        int4 wa = __ldcs(r0);
        int4 wb = __ldcs(r1);

        #pragma unroll 4
        for (int idx = 0; idx < KSEG / 4; idx++) {
            int4 wa_n, wb_n;
            if (idx < (KSEG / 4) - 1) {
                wa_n = __ldcs(r0 + idx + 1);
                wb_n = __ldcs(r1 + idx + 1);
            } else {
                wa_n = wa; wb_n = wb;
            }

            const ull a01 = fadd2(pack2(biasf(wa.x), biasf(wa.y)), C8);
            const ull a23 = fadd2(pack2(biasf(wa.z), biasf(wa.w)), C8);
            const ull b01 = fadd2(pack2(biasf(wb.x), biasf(wb.y)), C8);
            const ull b23 = fadd2(pack2(biasf(wb.z), biasf(wb.w)), C8);

            const int kp = idx * 2;
            #pragma unroll
            for (int mq = 0; mq < MROWS / 2; mq++) {
                const ulonglong2 xA = *reinterpret_cast<const ulonglong2*>(&xs[kp][2 * mq]);
                const ulonglong2 xB = *reinterpret_cast<const ulonglong2*>(&xs[kp + 1][2 * mq]);
                acc0[2 * mq]     = ffma2(xA.x, a01, acc0[2 * mq]);
                acc0[2 * mq + 1] = ffma2(xA.y, a01, acc0[2 * mq + 1]);
                acc0[2 * mq]     = ffma2(xB.x, a23, acc0[2 * mq]);
                acc0[2 * mq + 1] = ffma2(xB.y, a23, acc0[2 * mq + 1]);
                acc1[2 * mq]     = ffma2(xA.x, b01, acc1[2 * mq]);
                acc1[2 * mq + 1] = ffma2(xA.y, b01, acc1[2 * mq + 1]);
                acc1[2 * mq]     = ffma2(xB.x, b23, acc1[2 * mq]);
                acc1[2 * mq + 1] = ffma2(xB.y, b23, acc1[2 * mq + 1]);
            }
            wa = wa_n; wb = wb_n;
        }

        float* dst = &g_part[ks][0][0];
        #pragma unroll
        for (int m = 0; m < MROWS; m++) {
            float2 t0 = unpack2(acc0[m]);
            float2 t1 = unpack2(acc1[m]);
            dst[m * NTOT + N4 + nl0] = t0.x + t0.y;
            dst[m * NTOT + N4 + nl1] = t1.x + t1.y;
        }
    }
}

// ---------------- Kernel 3: slab reduce + s8 scale + inverse perm + bias ----------------
__global__ void epilogue_kernel(const float* __restrict__ s8,
                                const float* __restrict__ bias,
                                const int* __restrict__ inv_perm,
                                float* __restrict__ out)
{
    const int j = blockIdx.x * blockDim.x + threadIdx.x;   // 8192
    const int p = inv_perm[j];
    const float s = (p >= N4) ? s8[p - N4] : 1.0f;
    const float b = bias[j];
    #pragma unroll
    for (int m = 0; m < MROWS; m++) {
        float v = 0.0f;
        #pragma unroll
        for (int ksg = 0; ksg < KSEGS; ksg++)
            v += g_part[ksg][m][p];
        out[m * NTOT + j] = v * s + b;
    }
}

extern "C" void kernel_launch(void* const* d_in, const int* in_sizes, int n_in,
                              void* d_out, int out_size)
{
    const float* x    = (const float*)d_in[0];
    const int*   w4   = (const int*)  d_in[1];
    const float* s4   = (const float*)d_in[2];
    const int*   w8   = (const int*)  d_in[3];
    const float* s8   = (const float*)d_in[4];
    const float* awq  = (const float*)d_in[5];
    const float* bias = (const float*)d_in[6];
    const int*   ip   = (const int*)  d_in[7];
    float* out = (float*)d_out;

    prep_kernel<<<64, 256>>>(x, awq);

    dim3 grid(NBLK, KSEGS);
    gemv_kernel<<<grid, TPB>>>((const int4*)w4, s4, (const int4*)w8);

    epilogue_kernel<<<NTOT / 256, 256>>>(s8, bias, ip, out);
}

// round 6
// speedup vs baseline: 1.0903x; 1.0903x over previous
#include <cuda_runtime.h>
#include <cstdint>

#define KDIM  8192
#define N4    6144
#define N8    2048
#define NTOT  8192
#define MROWS 16
#define KSEGS 16
#define KSEG  512          // KDIM / KSEGS
#define NBLK  32           // 24 int4 + 8 int8 column blocks
#define TPB   256
#define CPB   256          // 1 column per thread

typedef unsigned long long ull;

// Scratch (device globals; no runtime allocation)
__device__ __align__(16) ull   g_x2p[KDIM / 2][MROWS];        // 512 KB, k-pair packed x2
__device__ __align__(16) float g_part[KSEGS][MROWS][NTOT];    // 8 MB partial slabs

// ---- Blackwell packed fp32 ops (sm_100+; ptxas never auto-emits these) ----
__device__ __forceinline__ ull ffma2(ull a, ull b, ull c) {
    ull d;
    asm("fma.rn.f32x2 %0, %1, %2, %3;" : "=l"(d) : "l"(a), "l"(b), "l"(c));
    return d;
}
__device__ __forceinline__ ull fadd2(ull a, ull b) {
    ull d;
    asm("add.rn.f32x2 %0, %1, %2;" : "=l"(d) : "l"(a), "l"(b));
    return d;
}
__device__ __forceinline__ ull fmul2(ull a, ull b) {
    ull d;
    asm("mul.rn.f32x2 %0, %1, %2;" : "=l"(d) : "l"(a), "l"(b));
    return d;
}
__device__ __forceinline__ ull pack2(float lo, float hi) {
    ull r;
    asm("mov.b64 %0, {%1, %2};" : "=l"(r) : "f"(lo), "f"(hi));
    return r;
}
__device__ __forceinline__ float2 unpack2(ull v) {
    float2 f;
    asm("mov.b64 {%0, %1}, %2;" : "=f"(f.x), "=f"(f.y) : "l"(v));
    return f;
}
// int (0 <= w < 2^22) -> float(2^23 + w), exact, one LOP3
__device__ __forceinline__ float biasf(int w) {
    return __uint_as_float(0x4B000000u | (unsigned)w);
}

// -------- Kernel 1: transpose+scale: g_x2p[kp][m] = pack(x[m][2kp]/awq[2kp], x[m][2kp+1]/awq[2kp+1]) --------
// Exactly 8192 threads: (kp 0..4095) x (m-half 0..1). NO extra threads — extras
// would alias the next kp row and race (R5 bug).
__global__ void prep_kernel(const float* __restrict__ x, const float* __restrict__ awq) {
    const int idx = blockIdx.x * blockDim.x + threadIdx.x;
    if (idx >= (KDIM / 2) * 2) return;
    const int kp = idx & 4095;
    const int mh = idx >> 12;          // 0 or 1 -> m rows 8mh..8mh+7
    const float2 a = *reinterpret_cast<const float2*>(awq + 2 * kp);
    ull p[8];
    #pragma unroll
    for (int i = 0; i < 8; i++) {
        const int m = mh * 8 + i;
        const float2 xv = *reinterpret_cast<const float2*>(x + (size_t)m * KDIM + 2 * kp);
        p[i] = pack2(xv.x / a.x, xv.y / a.y);
    }
    ulonglong2* dst = reinterpret_cast<ulonglong2*>(&g_x2p[kp][mh * 8]);
    #pragma unroll
    for (int q = 0; q < 4; q++)
        dst[q] = make_ulonglong2(p[2 * q], p[2 * q + 1]);
}

// ---------------- Kernel 2: mixed int4/int8 GEMV ----------------
// grid = (NBLK, KSEGS). Blocks 0..23: int4 cols. Blocks 24..31: uint8 cols.
// 1 col/thread; 16 m accumulators, k-pair packed f32x2 (32 regs of acc state).
__global__ void __launch_bounds__(TPB, 3) gemv_kernel(
    const int4* __restrict__ w4,   // w_int4 as int4 vectors
    const float* __restrict__ s4,  // s_int4 [N4][64]
    const int4* __restrict__ w8)   // w_uint8 as int4 vectors
{
    __shared__ ull xs[KSEG / 2][MROWS];   // 256 x 16 x 8B = 32 KB

    const int nb  = blockIdx.x;
    const int ks  = blockIdx.y;
    const int k0  = ks * KSEG;
    const int tid = threadIdx.x;

    // Stage x k-pair tile: contiguous 32 KB copy
    {
        const ulonglong2* src = reinterpret_cast<const ulonglong2*>(&g_x2p[k0 / 2][0]);
        ulonglong2* dst = reinterpret_cast<ulonglong2*>(&xs[0][0]);
        #pragma unroll
        for (int i = tid; i < (KSEG / 2) * MROWS / 2; i += TPB)
            dst[i] = src[i];
    }
    __syncthreads();

    ull acc[MROWS];
    #pragma unroll
    for (int m = 0; m < MROWS; m++) acc[m] = 0ull;

    if (nb < 24) {
        // ---------------- int4 path ----------------
        const int n = nb * CPB + tid;
        const int4* row = w4 + ((size_t)n * KDIM + k0) / 4;
        const ull C4 = pack2(-8388616.0f, -8388616.0f);   // -(2^23 + 8)

        #pragma unroll
        for (int g = 0; g < KSEG / 128; g++) {            // 4 groups of 128 k
            const float s = s4[n * (KDIM / 128) + (k0 >> 7) + g];
            const ull sp = pack2(s, s);

            #pragma unroll 2
            for (int it = 0; it < 32; it++) {             // one int4 = 4 k = 2 k-pairs
                const int idx = g * 32 + it;
                const int4 w = __ldcs(row + idx);
                // dequant, exact: ((2^23+w) - (2^23+8)) * s, k-pair packed
                const ull w01 = fmul2(fadd2(pack2(biasf(w.x), biasf(w.y)), C4), sp);
                const ull w23 = fmul2(fadd2(pack2(biasf(w.z), biasf(w.w)), C4), sp);

                const int kp = idx * 2;
                #pragma unroll
                for (int mq = 0; mq < MROWS / 2; mq++) {
                    const ulonglong2 xA = *reinterpret_cast<const ulonglong2*>(&xs[kp][2 * mq]);
                    const ulonglong2 xB = *reinterpret_cast<const ulonglong2*>(&xs[kp + 1][2 * mq]);
                    acc[2 * mq]     = ffma2(xA.x, w01, acc[2 * mq]);
                    acc[2 * mq + 1] = ffma2(xA.y, w01, acc[2 * mq + 1]);
                    acc[2 * mq]     = ffma2(xB.x, w23, acc[2 * mq]);
                    acc[2 * mq + 1] = ffma2(xB.y, w23, acc[2 * mq + 1]);
                }
            }
        }

        float* dst = &g_part[ks][0][0];
        #pragma unroll
        for (int m = 0; m < MROWS; m++) {
            float2 t = unpack2(acc[m]);
            dst[m * NTOT + n] = t.x + t.y;
        }
    } else {
        // ---------------- uint8 path: sum x2*(w-128); s8 deferred ----------------
        const int nl = (nb - 24) * CPB + tid;
        const int4* row = w8 + ((size_t)nl * KDIM + k0) / 4;
        const ull C8 = pack2(-8388736.0f, -8388736.0f);   // -(2^23 + 128)

        #pragma unroll 2
        for (int idx = 0; idx < KSEG / 4; idx++) {
            const int4 w = __ldcs(row + idx);
            const ull w01 = fadd2(pack2(biasf(w.x), biasf(w.y)), C8);
            const ull w23 = fadd2(pack2(biasf(w.z), biasf(w.w)), C8);

            const int kp = idx * 2;
            #pragma unroll
            for (int mq = 0; mq < MROWS / 2; mq++) {
                const ulonglong2 xA = *reinterpret_cast<const ulonglong2*>(&xs[kp][2 * mq]);
                const ulonglong2 xB = *reinterpret_cast<const ulonglong2*>(&xs[kp + 1][2 * mq]);
                acc[2 * mq]     = ffma2(xA.x, w01, acc[2 * mq]);
                acc[2 * mq + 1] = ffma2(xA.y, w01, acc[2 * mq + 1]);
                acc[2 * mq]     = ffma2(xB.x, w23, acc[2 * mq]);
                acc[2 * mq + 1] = ffma2(xB.y, w23, acc[2 * mq + 1]);
            }
        }

        float* dst = &g_part[ks][0][0];
        #pragma unroll
        for (int m = 0; m < MROWS; m++) {
            float2 t = unpack2(acc[m]);
            dst[m * NTOT + N4 + nl] = t.x + t.y;
        }
    }
}

// ---------------- Kernel 3: slab reduce + s8 scale + inverse perm + bias ----------------
__global__ void epilogue_kernel(const float* __restrict__ s8,
                                const float* __restrict__ bias,
                                const int* __restrict__ inv_perm,
                                float* __restrict__ out)
{
    const int j = blockIdx.x * blockDim.x + threadIdx.x;   // 8192
    const int p = inv_perm[j];
    const float s = (p >= N4) ? s8[p - N4] : 1.0f;
    const float b = bias[j];
    #pragma unroll
    for (int m = 0; m < MROWS; m++) {
        float v = 0.0f;
        #pragma unroll
        for (int ksg = 0; ksg < KSEGS; ksg++)
            v += g_part[ksg][m][p];
        out[m * NTOT + j] = v * s + b;
    }
}

extern "C" void kernel_launch(void* const* d_in, const int* in_sizes, int n_in,
                              void* d_out, int out_size)
{
    const float* x    = (const float*)d_in[0];
    const int*   w4   = (const int*)  d_in[1];
    const float* s4   = (const float*)d_in[2];
    const int*   w8   = (const int*)  d_in[3];
    const float* s8   = (const float*)d_in[4];
    const float* awq  = (const float*)d_in[5];
    const float* bias = (const float*)d_in[6];
    const int*   ip   = (const int*)  d_in[7];
    float* out = (float*)d_out;

    prep_kernel<<<32, 256>>>(x, awq);   // exactly 8192 threads

    dim3 grid(NBLK, KSEGS);
    gemv_kernel<<<grid, TPB>>>((const int4*)w4, s4, (const int4*)w8);

    epilogue_kernel<<<NTOT / 256, 256>>>(s8, bias, ip, out);
}

// round 7
// speedup vs baseline: 1.8041x; 1.6547x over previous
#include <cuda_runtime.h>
#include <cstdint>

#define KDIM  8192
#define N4    6144
#define N8    2048
#define NTOT  8192
#define MROWS 16
#define KSEGS 32
#define KSEG  256          // KDIM / KSEGS
#define NBLK  16           // 12 int4 + 4 int8 column blocks
#define TPB   128
#define CPT   4            // columns per thread
#define CPB   (TPB * CPT)  // 512 columns per block

typedef unsigned long long ull;

// Scratch (device globals; no runtime allocation)
__device__ __align__(16) float  g_x2t[KDIM * MROWS];              // 512 KB, [k][m]
__device__ __align__(16) float2 g_part[KSEGS][MROWS / 2][NTOT];   // 16 MB, [ks][mp][n]
__device__ __align__(16) float2 g_sum[MROWS / 2][NTOT];           // 512 KB, [mp][n]

// ---- Blackwell packed fp32 ops (sm_100+; ptxas never auto-emits these) ----
__device__ __forceinline__ ull ffma2(ull a, ull b, ull c) {
    ull d;
    asm("fma.rn.f32x2 %0, %1, %2, %3;" : "=l"(d) : "l"(a), "l"(b), "l"(c));
    return d;
}
__device__ __forceinline__ ull pack2(float lo, float hi) {
    ull r;
    asm("mov.b64 %0, {%1, %2};" : "=l"(r) : "f"(lo), "f"(hi));
    return r;
}
__device__ __forceinline__ float2 unpack2(ull v) {
    float2 f;
    asm("mov.b64 {%0, %1}, %2;" : "=f"(f.x), "=f"(f.y) : "l"(v));
    return f;
}
// int (0 <= w < 2^22) -> float(2^23 + w), exact, one LOP3
__device__ __forceinline__ float biasf(int w) {
    return __uint_as_float(0x4B000000u | (unsigned)w);
}

// -------- Kernel 1: transpose+scale: g_x2t[k*16+m] = x[m][k] / awq[k] --------
// 32768 threads: m-quad slow (idx>>13), k fast (idx&8191) -> coalesced x reads.
__global__ void prep_kernel(const float* __restrict__ x, const float* __restrict__ awq) {
    const int idx = blockIdx.x * blockDim.x + threadIdx.x;
    const int k  = idx & (KDIM - 1);
    const int mq = idx >> 13;              // 0..3 -> m rows 4mq..4mq+3
    const float inva = awq[k];
    float v[4];
    #pragma unroll
    for (int i = 0; i < 4; i++)
        v[i] = x[(size_t)(4 * mq + i) * KDIM + k] / inva;
    *reinterpret_cast<float4*>(&g_x2t[(size_t)k * MROWS + 4 * mq]) =
        make_float4(v[0], v[1], v[2], v[3]);
}

// ---------------- Kernel 2: mixed int4/int8 GEMV ----------------
// grid = (NBLK, KSEGS). Blocks 0..11: int4 cols. Blocks 12..15: uint8 cols.
// 4 cols/thread (amortizes each broadcast LDS.128 over 4 columns),
// 16 m rows as m-pair-packed f32x2 accumulators (64 regs).
__global__ void __launch_bounds__(TPB, 3) gemv_kernel(
    const int4* __restrict__ w4,   // w_int4 as int4 vectors
    const float* __restrict__ s4,  // s_int4 [N4][64]
    const int4* __restrict__ w8)   // w_uint8 as int4 vectors
{
    __shared__ ull xs[KSEG][MROWS / 2];   // [k][m-pair], 256*8*8B = 16 KB

    const int nb  = blockIdx.x;
    const int ks  = blockIdx.y;
    const int k0  = ks * KSEG;
    const int tid = threadIdx.x;

    // Stage transposed x tile: 16 KB contiguous copy
    {
        const ulonglong2* src = reinterpret_cast<const ulonglong2*>(g_x2t + (size_t)k0 * MROWS);
        ulonglong2* dst = reinterpret_cast<ulonglong2*>(&xs[0][0]);
        #pragma unroll
        for (int i = tid; i < KSEG * MROWS / 4; i += TPB)
            dst[i] = src[i];
    }
    __syncthreads();

    ull acc[CPT][MROWS / 2];
    #pragma unroll
    for (int c = 0; c < CPT; c++)
        #pragma unroll
        for (int mp = 0; mp < MROWS / 2; mp++) acc[c][mp] = 0ull;

    if (nb < 12) {
        // ---------------- int4 path ----------------
        int n[CPT];
        const int4* row[CPT];
        #pragma unroll
        for (int c = 0; c < CPT; c++) {
            n[c] = nb * CPB + c * TPB + tid;          // coalesced across warp
            row[c] = w4 + ((size_t)n[c] * KDIM + k0) / 4;
        }
        const float C4 = -8388616.0f;                 // -(2^23 + 8)

        #pragma unroll
        for (int g = 0; g < KSEG / 128; g++) {        // 2 groups of 128 k
            float s[CPT];
            #pragma unroll
            for (int c = 0; c < CPT; c++)
                s[c] = s4[n[c] * (KDIM / 128) + (k0 >> 7) + g];

            #pragma unroll 2
            for (int it = 0; it < 32; it++) {         // 4 k per iteration
                const int idx = g * 32 + it;
                int4 w[CPT];
                #pragma unroll
                for (int c = 0; c < CPT; c++) w[c] = __ldcs(row[c] + idx);   // MLP=4

                #pragma unroll
                for (int j = 0; j < 4; j++) {
                    const int k = idx * 4 + j;
                    ulonglong2 xa = *reinterpret_cast<const ulonglong2*>(&xs[k][0]);
                    ulonglong2 xb = *reinterpret_cast<const ulonglong2*>(&xs[k][2]);
                    ulonglong2 xc = *reinterpret_cast<const ulonglong2*>(&xs[k][4]);
                    ulonglong2 xd = *reinterpret_cast<const ulonglong2*>(&xs[k][6]);
                    #pragma unroll
                    for (int c = 0; c < CPT; c++) {
                        const int wi = (j == 0) ? w[c].x : (j == 1) ? w[c].y
                                     : (j == 2) ? w[c].z : w[c].w;
                        const float wd = (biasf(wi) + C4) * s[c];   // exact (w-8)*s
                        const ull wdd = pack2(wd, wd);
                        acc[c][0] = ffma2(xa.x, wdd, acc[c][0]);
                        acc[c][1] = ffma2(xa.y, wdd, acc[c][1]);
                        acc[c][2] = ffma2(xb.x, wdd, acc[c][2]);
                        acc[c][3] = ffma2(xb.y, wdd, acc[c][3]);
                        acc[c][4] = ffma2(xc.x, wdd, acc[c][4]);
                        acc[c][5] = ffma2(xc.y, wdd, acc[c][5]);
                        acc[c][6] = ffma2(xd.x, wdd, acc[c][6]);
                        acc[c][7] = ffma2(xd.y, wdd, acc[c][7]);
                    }
                }
            }
        }

        #pragma unroll
        for (int c = 0; c < CPT; c++)
            #pragma unroll
            for (int mp = 0; mp < MROWS / 2; mp++)
                g_part[ks][mp][n[c]] = unpack2(acc[c][mp]);
    } else {
        // ---------------- uint8 path: sum x2*(w-128); s8 deferred ----------------
        int nl[CPT];
        const int4* row[CPT];
        #pragma unroll
        for (int c = 0; c < CPT; c++) {
            nl[c] = (nb - 12) * CPB + c * TPB + tid;
            row[c] = w8 + ((size_t)nl[c] * KDIM + k0) / 4;
        }
        const float C8 = -8388736.0f;                 // -(2^23 + 128)

        #pragma unroll 2
        for (int idx = 0; idx < KSEG / 4; idx++) {
            int4 w[CPT];
            #pragma unroll
            for (int c = 0; c < CPT; c++) w[c] = __ldcs(row[c] + idx);

            #pragma unroll
            for (int j = 0; j < 4; j++) {
                const int k = idx * 4 + j;
                ulonglong2 xa = *reinterpret_cast<const ulonglong2*>(&xs[k][0]);
                ulonglong2 xb = *reinterpret_cast<const ulonglong2*>(&xs[k][2]);
                ulonglong2 xc = *reinterpret_cast<const ulonglong2*>(&xs[k][4]);
                ulonglong2 xd = *reinterpret_cast<const ulonglong2*>(&xs[k][6]);
                #pragma unroll
                for (int c = 0; c < CPT; c++) {
                    const int wi = (j == 0) ? w[c].x : (j == 1) ? w[c].y
                                 : (j == 2) ? w[c].z : w[c].w;
                    const float wd = biasf(wi) + C8;            // exact w-128
                    const ull wdd = pack2(wd, wd);
                    acc[c][0] = ffma2(xa.x, wdd, acc[c][0]);
                    acc[c][1] = ffma2(xa.y, wdd, acc[c][1]);
                    acc[c][2] = ffma2(xb.x, wdd, acc[c][2]);
                    acc[c][3] = ffma2(xb.y, wdd, acc[c][3]);
                    acc[c][4] = ffma2(xc.x, wdd, acc[c][4]);
                    acc[c][5] = ffma2(xc.y, wdd, acc[c][5]);
                    acc[c][6] = ffma2(xd.x, wdd, acc[c][6]);
                    acc[c][7] = ffma2(xd.y, wdd, acc[c][7]);
                }
            }
        }

        #pragma unroll
        for (int c = 0; c < CPT; c++)
            #pragma unroll
            for (int mp = 0; mp < MROWS / 2; mp++)
                g_part[ks][mp][N4 + nl[c]] = unpack2(acc[c][mp]);
    }
}

// -------- Kernel 3a: coalesced slab reduction: g_sum[mp][n] = sum_ks g_part[ks][mp][n] --------
// 65536 threads, one per (mp, n); reads coalesced along n.
__global__ void sum_kernel() {
    const int idx = blockIdx.x * blockDim.x + threadIdx.x;
    const int n  = idx & (NTOT - 1);
    const int mp = idx >> 13;              // 0..7
    float2 v = make_float2(0.0f, 0.0f);
    #pragma unroll
    for (int ks = 0; ks < KSEGS; ks++) {
        float2 t = g_part[ks][mp][n];
        v.x += t.x;
        v.y += t.y;
    }
    g_sum[mp][n] = v;
}

// -------- Kernel 3b: permute + s8 scale + bias --------
__global__ void permute_kernel(const float* __restrict__ s8,
                               const float* __restrict__ bias,
                               const int* __restrict__ inv_perm,
                               float* __restrict__ out)
{
    const int j = blockIdx.x * blockDim.x + threadIdx.x;   // 8192
    const int p = inv_perm[j];
    const float s = (p >= N4) ? s8[p - N4] : 1.0f;
    const float b = bias[j];
    #pragma unroll
    for (int mp = 0; mp < MROWS / 2; mp++) {
        const float2 v = g_sum[mp][p];
        out[(2 * mp)     * NTOT + j] = v.x * s + b;
        out[(2 * mp + 1) * NTOT + j] = v.y * s + b;
    }
}

extern "C" void kernel_launch(void* const* d_in, const int* in_sizes, int n_in,
                              void* d_out, int out_size)
{
    const float* x    = (const float*)d_in[0];
    const int*   w4   = (const int*)  d_in[1];
    const float* s4   = (const float*)d_in[2];
    const int*   w8   = (const int*)  d_in[3];
    const float* s8   = (const float*)d_in[4];
    const float* awq  = (const float*)d_in[5];
    const float* bias = (const float*)d_in[6];
    const int*   ip   = (const int*)  d_in[7];
    float* out = (float*)d_out;

    prep_kernel<<<128, 256>>>(x, awq);      // exactly 32768 threads

    dim3 grid(NBLK, KSEGS);                 // 512 blocks
    gemv_kernel<<<grid, TPB>>>((const int4*)w4, s4, (const int4*)w8);

    sum_kernel<<<256, 256>>>();             // exactly 65536 threads
    permute_kernel<<<NTOT / 256, 256>>>(s8, bias, ip, out);
}